// round 8
// baseline (speedup 1.0000x reference)
#include <cuda_runtime.h>
#include <cuda_fp16.h>
#include <cstdint>
#include <math.h>

// Problem shape (fixed)
#define NB   4
#define SEQ  2048
#define DIN  1024
#define DH   1024

// ---------------------------------------------------------------------------
// Scratch (__device__ globals; no allocs allowed)
// ---------------------------------------------------------------------------
__device__ __half g_xh [(size_t)NB * SEQ * DIN];      // fp16 x            (16 MB)
__device__ __half g_Wqk[(size_t)2 * DH * DIN];        // [Wq; Wk] fp16     (4 MB)
__device__ __half g_Wv [(size_t)DH * DIN];            // fp16              (2 MB)
__device__ __half g_QK [(size_t)NB * SEQ * 2 * DH];   // [Q | K] fp16      (32 MB)
__device__ __half g_Vt [(size_t)NB * DH * SEQ];       // V^T fp16          (16 MB)
__device__ float  g_Sc [(size_t)NB * SEQ * SEQ];      // scores fp32       (64 MB)
__device__ __half g_At [(size_t)NB * SEQ * SEQ];      // attn fp16         (32 MB)

// ---------------------------------------------------------------------------
__device__ __forceinline__ uint32_t smem_u32(const void* p) {
    uint32_t a;
    asm("{ .reg .u64 t; cvta.to.shared.u64 t, %1; cvt.u32.u64 %0, t; }"
        : "=r"(a) : "l"(p));
    return a;
}

#define LDMATRIX_X4(r0, r1, r2, r3, addr)                                      \
    asm volatile("ldmatrix.sync.aligned.m8n8.x4.shared.b16 {%0,%1,%2,%3}, [%4];" \
                 : "=r"(r0), "=r"(r1), "=r"(r2), "=r"(r3) : "r"(addr))

// ---------------------------------------------------------------------------
// fp16 m16n8k16 NT GEMM:  C = alpha * A @ B^T
//   A:[M,K] ldA halfs, B:[N,K] ldB halfs (both K-contiguous), fp32 accum.
//   CTA tile 128x256x64, 8 warps (2x4 grid of 64x64 warp tiles), 3-stage
//   cp.async, XOR swizzle, ldmatrix.x4. OUT_HALF: C is __half else float.
// ---------------------------------------------------------------------------
constexpr int BM = 128, BN = 256, BK = 64, NST = 3;
constexpr int TILEA_H  = BM * BK;                    // 8192 halfs = 16 KB
constexpr int TILEB_H  = BN * BK;                    // 16384 halfs = 32 KB
constexpr int STAGE_H  = TILEA_H + TILEB_H;          // 48 KB per stage
constexpr int SMEM_BYTES = NST * STAGE_H * 2;        // 147456 B

template <bool OUT_HALF>
__global__ __launch_bounds__(256, 1)
void gemm_h16_nt(const __half* __restrict__ A, const __half* __restrict__ B,
                 void* __restrict__ Cv, int K,
                 int ldA, int ldB, int ldC, float alpha,
                 size_t sA, size_t sB, size_t sC)
{
    extern __shared__ __align__(16) __half sm[];

    const int tid  = threadIdx.x;
    const int wid  = tid >> 5;
    const int lane = tid & 31;
    const int g    = lane >> 2;      // 0..7
    const int tig  = lane & 3;       // 0..3

    const int wm = wid >> 2;         // 0..1 : 64-row warp slab
    const int wn = wid & 3;          // 0..3 : 64-col warp slab

    const __half* Ab = A + sA * blockIdx.z;
    const __half* Bb = B + sB * blockIdx.z;
    const int bm = blockIdx.y * BM;
    const int bn = blockIdx.x * BN;
    const int KT = K / BK;

    const uint32_t smem_base = smem_u32(sm);

    // ldmatrix per-lane row/chunk precompute (row&7 == lane&7 for all bases).
    const int xorv = lane & 7;
    // A x4: matrices (r..r+7,c0),(r+8..r+15,c0),(r..r+7,c1),(r+8..,c1)
    const int rowA = wm * 64 + (lane & 7) + ((lane >> 3) & 1) * 8;
    const int selA = lane >> 4;                   // 0:c0 1:c1
    // B x4: matrices (rb..rb+7,c0),(rb..,c1),(rb+8..,c0),(rb+8..,c1)
    const int rowB = wn * 64 + (lane & 7) + ((lane >> 4) & 1) * 8;
    const int selB = (lane >> 3) & 1;             // 0:c0 1:c1

    // Stage loader. Rows are 64 halfs = 128 B = 8 x 16B chunks.
    // Chunk c of row r stored at physical chunk c ^ (r & 7).
    // A: 128 rows (4 iters x 256 thr), B: 256 rows (8 iters).
#define LOAD_STAGE(s) do {                                                     \
        const uint32_t _aB = smem_base + (uint32_t)(((s) % NST) * STAGE_H * 2); \
        const uint32_t _bB = _aB + (uint32_t)(TILEA_H * 2);                    \
        _Pragma("unroll")                                                      \
        for (int _i = 0; _i < 4; _i++) {                                       \
            const int _idx = _i * 256 + tid;                                   \
            const int _row = _idx >> 3;                                        \
            const int _seg = _idx & 7;                                         \
            const uint32_t _soff = (uint32_t)(_row * 128 +                     \
                                   ((_seg ^ (_row & 7)) << 4));                \
            const __half* _ga = Ab + (size_t)(bm + _row) * ldA + (s) * BK + _seg * 8; \
            asm volatile("cp.async.cg.shared.global [%0], [%1], 16;"           \
                         :: "r"(_aB + _soff), "l"(_ga));                       \
        }                                                                      \
        _Pragma("unroll")                                                      \
        for (int _i = 0; _i < 8; _i++) {                                       \
            const int _idx = _i * 256 + tid;                                   \
            const int _row = _idx >> 3;                                        \
            const int _seg = _idx & 7;                                         \
            const uint32_t _soff = (uint32_t)(_row * 128 +                     \
                                   ((_seg ^ (_row & 7)) << 4));                \
            const __half* _gb = Bb + (size_t)(bn + _row) * ldB + (s) * BK + _seg * 8; \
            asm volatile("cp.async.cg.shared.global [%0], [%1], 16;"           \
                         :: "r"(_bB + _soff), "l"(_gb));                       \
        }                                                                      \
        asm volatile("cp.async.commit_group;" ::: "memory");                   \
    } while (0)

    float acc[4][8][4];
    #pragma unroll
    for (int i = 0; i < 4; i++)
        #pragma unroll
        for (int j = 0; j < 8; j++)
            #pragma unroll
            for (int r = 0; r < 4; r++) acc[i][j][r] = 0.0f;

    LOAD_STAGE(0);
    LOAD_STAGE(1);

    for (int k0 = 0; k0 < KT; k0++) {
        if (k0 + 1 < KT) asm volatile("cp.async.wait_group 1;" ::: "memory");
        else             asm volatile("cp.async.wait_group 0;" ::: "memory");
        __syncthreads();

        if (k0 + 2 < KT) LOAD_STAGE(k0 + 2);

        const uint32_t stA = smem_base + (uint32_t)((k0 % NST) * STAGE_H * 2);
        const uint32_t stB = stA + (uint32_t)(TILEA_H * 2);
        const uint32_t aRowAddr = stA + (uint32_t)(rowA * 128);
        const uint32_t bRowAddr = stB + (uint32_t)(rowB * 128);

        #pragma unroll
        for (int ks = 0; ks < BK / 16; ks++) {
            const uint32_t offA = (uint32_t)(((2 * ks + selA) ^ xorv) << 4);
            const uint32_t offB = (uint32_t)(((2 * ks + selB) ^ xorv) << 4);
            uint32_t a[4][4], b[8][2];
            #pragma unroll
            for (int mf = 0; mf < 4; mf++)
                LDMATRIX_X4(a[mf][0], a[mf][1], a[mf][2], a[mf][3],
                            aRowAddr + (uint32_t)(mf * 16 * 128) + offA);
            #pragma unroll
            for (int p = 0; p < 4; p++)
                LDMATRIX_X4(b[2 * p][0], b[2 * p][1], b[2 * p + 1][0], b[2 * p + 1][1],
                            bRowAddr + (uint32_t)(p * 16 * 128) + offB);
            #pragma unroll
            for (int mf = 0; mf < 4; mf++)
                #pragma unroll
                for (int nf = 0; nf < 8; nf++)
                    asm volatile(
                        "mma.sync.aligned.m16n8k16.row.col.f32.f16.f16.f32 "
                        "{%0,%1,%2,%3}, {%4,%5,%6,%7}, {%8,%9}, {%0,%1,%2,%3};"
                        : "+f"(acc[mf][nf][0]), "+f"(acc[mf][nf][1]),
                          "+f"(acc[mf][nf][2]), "+f"(acc[mf][nf][3])
                        : "r"(a[mf][0]), "r"(a[mf][1]), "r"(a[mf][2]), "r"(a[mf][3]),
                          "r"(b[nf][0]), "r"(b[nf][1]));
        }
    }
#undef LOAD_STAGE

    // Epilogue: direct float2 / half2 stores (32B sectors fully covered).
    const int mBase = bm + wm * 64 + g;
    const int nBase = bn + wn * 64 + 2 * tig;
    #pragma unroll
    for (int mf = 0; mf < 4; mf++) {
        #pragma unroll
        for (int nf = 0; nf < 8; nf++) {
            const float v0 = acc[mf][nf][0] * alpha, v1 = acc[mf][nf][1] * alpha;
            const float v2 = acc[mf][nf][2] * alpha, v3 = acc[mf][nf][3] * alpha;
            const size_t r0 = (size_t)(mBase + mf * 16) * ldC + nBase + nf * 8;
            const size_t r1 = r0 + 8 * (size_t)ldC;
            if (OUT_HALF) {
                __half* Ch = (__half*)Cv + sC * blockIdx.z;
                *reinterpret_cast<__half2*>(&Ch[r0]) =
                    __float22half2_rn(make_float2(v0, v1));
                *reinterpret_cast<__half2*>(&Ch[r1]) =
                    __float22half2_rn(make_float2(v2, v3));
            } else {
                float* Cf = (float*)Cv + sC * blockIdx.z;
                *reinterpret_cast<float2*>(&Cf[r0]) = make_float2(v0, v1);
                *reinterpret_cast<float2*>(&Cf[r1]) = make_float2(v2, v3);
            }
        }
    }
}

// ---------------------------------------------------------------------------
// Fused fp32 -> fp16 convert for x, Wq, Wk, Wv in ONE launch.
// Block map: [0,4096) x ; [4096,4608) Wq ; [4608,5120) Wk ; [5120,5632) Wv.
// ---------------------------------------------------------------------------
__global__ __launch_bounds__(256)
void cvt_all_kernel(const float4* __restrict__ x,  uint4* __restrict__ xh,
                    const float4* __restrict__ wq, const float4* __restrict__ wk,
                    uint4* __restrict__ wqk,
                    const float4* __restrict__ wv, uint4* __restrict__ wvh)
{
    const int b = blockIdx.x;
    const float4* src;
    uint4* dst;
    int off;
    if (b < 4096)      { src = x;  dst = xh;  off = b; }
    else if (b < 4608) { src = wq; dst = wqk; off = b - 4096; }
    else if (b < 5120) { src = wk; dst = wqk + (size_t)(DH * DIN) / 8; off = b - 4608; }
    else               { src = wv; dst = wvh; off = b - 5120; }

    const int i = off * 256 + threadIdx.x;
    const float4 u = src[2 * i], v = src[2 * i + 1];
    __half2 h0 = __float22half2_rn(make_float2(u.x, u.y));
    __half2 h1 = __float22half2_rn(make_float2(u.z, u.w));
    __half2 h2 = __float22half2_rn(make_float2(v.x, v.y));
    __half2 h3 = __float22half2_rn(make_float2(v.z, v.w));
    uint4 o;
    o.x = *reinterpret_cast<uint32_t*>(&h0);
    o.y = *reinterpret_cast<uint32_t*>(&h1);
    o.z = *reinterpret_cast<uint32_t*>(&h2);
    o.w = *reinterpret_cast<uint32_t*>(&h3);
    dst[i] = o;
}

// ---------------------------------------------------------------------------
// Row softmax: read fp32 scores, write fp16 attn.
// ---------------------------------------------------------------------------
__global__ __launch_bounds__(256)
void softmax_kernel(const float* __restrict__ S, __half* __restrict__ P)
{
    const float* row = S + (size_t)blockIdx.x * SEQ;
    __half*     orow = P + (size_t)blockIdx.x * SEQ;
    const int tid  = threadIdx.x;
    const int lane = tid & 31;
    const int warp = tid >> 5;

    float4 v0 = reinterpret_cast<const float4*>(row)[2 * tid];
    float4 v1 = reinterpret_cast<const float4*>(row)[2 * tid + 1];

    __shared__ float red[8];

    float m = fmaxf(fmaxf(fmaxf(v0.x, v0.y), fmaxf(v0.z, v0.w)),
                    fmaxf(fmaxf(v1.x, v1.y), fmaxf(v1.z, v1.w)));
    #pragma unroll
    for (int o = 16; o > 0; o >>= 1) m = fmaxf(m, __shfl_xor_sync(0xFFFFFFFFu, m, o));
    if (lane == 0) red[warp] = m;
    __syncthreads();
    m = red[0];
    #pragma unroll
    for (int w = 1; w < 8; w++) m = fmaxf(m, red[w]);
    __syncthreads();

    v0.x = __expf(v0.x - m); v0.y = __expf(v0.y - m);
    v0.z = __expf(v0.z - m); v0.w = __expf(v0.w - m);
    v1.x = __expf(v1.x - m); v1.y = __expf(v1.y - m);
    v1.z = __expf(v1.z - m); v1.w = __expf(v1.w - m);

    float s = (v0.x + v0.y + v0.z + v0.w) + (v1.x + v1.y + v1.z + v1.w);
    #pragma unroll
    for (int o = 16; o > 0; o >>= 1) s += __shfl_xor_sync(0xFFFFFFFFu, s, o);
    if (lane == 0) red[warp] = s;
    __syncthreads();
    s = red[0];
    #pragma unroll
    for (int w = 1; w < 8; w++) s += red[w];

    const float inv = 1.0f / s;
    __half2 h0 = __float22half2_rn(make_float2(v0.x * inv, v0.y * inv));
    __half2 h1 = __float22half2_rn(make_float2(v0.z * inv, v0.w * inv));
    __half2 h2 = __float22half2_rn(make_float2(v1.x * inv, v1.y * inv));
    __half2 h3 = __float22half2_rn(make_float2(v1.z * inv, v1.w * inv));
    uint4 o;
    o.x = *reinterpret_cast<uint32_t*>(&h0);
    o.y = *reinterpret_cast<uint32_t*>(&h1);
    o.z = *reinterpret_cast<uint32_t*>(&h2);
    o.w = *reinterpret_cast<uint32_t*>(&h3);
    reinterpret_cast<uint4*>(orow)[tid] = o;
}

// ---------------------------------------------------------------------------
extern "C" void kernel_launch(void* const* d_in, const int* in_sizes, int n_in,
                              void* d_out, int out_size)
{
    (void)in_sizes; (void)n_in; (void)out_size;

    const float* x  = (const float*)d_in[0];
    const float* Wq = (const float*)d_in[1];
    const float* Wk = (const float*)d_in[2];
    const float* Wv = (const float*)d_in[3];
    float*       out = (float*)d_out;

    __half *xh, *wqk, *wv, *QK, *Vt, *At;
    float *Sc;
    cudaGetSymbolAddress((void**)&xh,  g_xh);
    cudaGetSymbolAddress((void**)&wqk, g_Wqk);
    cudaGetSymbolAddress((void**)&wv,  g_Wv);
    cudaGetSymbolAddress((void**)&QK,  g_QK);
    cudaGetSymbolAddress((void**)&Vt,  g_Vt);
    cudaGetSymbolAddress((void**)&Sc,  g_Sc);
    cudaGetSymbolAddress((void**)&At,  g_At);

    cudaFuncSetAttribute(gemm_h16_nt<true>,
                         cudaFuncAttributeMaxDynamicSharedMemorySize, SMEM_BYTES);
    cudaFuncSetAttribute(gemm_h16_nt<false>,
                         cudaFuncAttributeMaxDynamicSharedMemorySize, SMEM_BYTES);

    // 0) convert all inputs to fp16, one launch
    cvt_all_kernel<<<5632, 256>>>((const float4*)x,  (uint4*)xh,
                                  (const float4*)Wq, (const float4*)Wk,
                                  (uint4*)wqk,
                                  (const float4*)Wv, (uint4*)wv);

    // 1) [Q|K] = xh @ [Wq;Wk]^T : one GEMM, N = 2*DH, fp16 out
    {
        dim3 grid((2 * DH) / BN, (NB * SEQ) / BM, 1);     // (8, 64)
        gemm_h16_nt<true><<<grid, 256, SMEM_BYTES>>>(xh, wqk, QK, DIN,
                                                     DIN, DIN, 2 * DH, 1.0f,
                                                     0, 0, 0);
    }

    // 2) V^T_b = Wv @ x_b^T : M=DH, N=SEQ, K=DIN (per batch), fp16 out
    {
        dim3 grid(SEQ / BN, DH / BM, NB);                 // (8, 8, 4)
        gemm_h16_nt<true><<<grid, 256, SMEM_BYTES>>>(wv, xh, Vt, DIN,
                                                     DIN, DIN, SEQ, 1.0f,
                                                     0, (size_t)SEQ * DIN,
                                                     (size_t)DH * SEQ);
    }

    // 3) scores_b = (Q_b @ K_b^T) / sqrt(SEQ), fp32 out
    {
        const float scale = 1.0f / sqrtf((float)SEQ);
        dim3 grid(SEQ / BN, SEQ / BM, NB);                // (8, 16, 4)
        gemm_h16_nt<false><<<grid, 256, SMEM_BYTES>>>(QK, QK + DH, Sc, DH,
                                                      2 * DH, 2 * DH, SEQ, scale,
                                                      (size_t)SEQ * 2 * DH,
                                                      (size_t)SEQ * 2 * DH,
                                                      (size_t)SEQ * SEQ);
    }

    // 4) softmax: fp32 scores -> fp16 attn
    softmax_kernel<<<NB * SEQ, 256>>>(Sc, At);

    // 5) out_b = attn_b @ (V^T_b)^T : M=SEQ, N=DH, K=SEQ, fp32 out
    {
        dim3 grid(DH / BN, SEQ / BM, NB);                 // (4, 16, 4)
        gemm_h16_nt<false><<<grid, 256, SMEM_BYTES>>>(At, Vt, out, SEQ,
                                                      SEQ, SEQ, DH, 1.0f,
                                                      (size_t)SEQ * SEQ,
                                                      (size_t)DH * SEQ,
                                                      (size_t)SEQ * DH);
    }
}

// round 9
// speedup vs baseline: 1.1376x; 1.1376x over previous
#include <cuda_runtime.h>
#include <cuda_fp16.h>
#include <cstdint>
#include <math.h>

// Problem shape (fixed)
#define NB   4
#define SEQ  2048
#define DIN  1024
#define DH   1024

// ---------------------------------------------------------------------------
// Scratch (__device__ globals; no allocs allowed)
// ---------------------------------------------------------------------------
__device__ __half g_xh [(size_t)NB * SEQ * DIN];      // fp16 x            (16 MB)
__device__ __half g_Wqk[(size_t)2 * DH * DIN];        // [Wq; Wk] fp16     (4 MB)
__device__ __half g_Wv [(size_t)DH * DIN];            // fp16              (2 MB)
__device__ __half g_QK [(size_t)NB * SEQ * 2 * DH];   // [Q | K] fp16      (32 MB)
__device__ __half g_Vt [(size_t)NB * DH * SEQ];       // V^T fp16          (16 MB)
__device__ float  g_Sc [(size_t)NB * SEQ * SEQ];      // scores fp32       (64 MB)
__device__ __half g_At [(size_t)NB * SEQ * SEQ];      // attn fp16         (32 MB)

// ---------------------------------------------------------------------------
__device__ __forceinline__ uint32_t smem_u32(const void* p) {
    uint32_t a;
    asm("{ .reg .u64 t; cvta.to.shared.u64 t, %1; cvt.u32.u64 %0, t; }"
        : "=r"(a) : "l"(p));
    return a;
}

#define LDMATRIX_X4(r0, r1, r2, r3, addr)                                      \
    asm volatile("ldmatrix.sync.aligned.m8n8.x4.shared.b16 {%0,%1,%2,%3}, [%4];" \
                 : "=r"(r0), "=r"(r1), "=r"(r2), "=r"(r3) : "r"(addr))

// ---------------------------------------------------------------------------
// fp16 m16n8k16 NT GEMM:  C = alpha * A @ B^T
//   A:[M,K] ldA halfs, B:[N,K] ldB halfs (both K-contiguous), fp32 accum.
//   Tile 128x128x64, 8 warps (64x32 warp tile), 3-stage cp.async (issuance
//   spread across the ks loop), XOR swizzle, ldmatrix.x4.
//   OUT_HALF: C is __half else float.
// ---------------------------------------------------------------------------
constexpr int BM = 128, BN = 128, BK = 64, NST = 3;
constexpr int TILE_H  = BM * BK;                 // 8192 halfs = 16 KB per operand
constexpr int STAGE_H = 2 * TILE_H;              // 32 KB per stage
constexpr int SMEM_BYTES = NST * STAGE_H * 2;    // 98304 B

template <bool OUT_HALF>
__global__ __launch_bounds__(256, 2)
void gemm_h16_nt(const __half* __restrict__ A, const __half* __restrict__ B,
                 void* __restrict__ Cv, int K,
                 int ldA, int ldB, int ldC, float alpha,
                 size_t sA, size_t sB, size_t sC)
{
    extern __shared__ __align__(16) __half sm[];

    const int tid  = threadIdx.x;
    const int wid  = tid >> 5;
    const int lane = tid & 31;
    const int g    = lane >> 2;      // 0..7
    const int tig  = lane & 3;       // 0..3

    const int wm = wid >> 2;         // 0..1 : 64-row warp slab
    const int wn = wid & 3;          // 0..3 : 32-col warp slab

    const __half* Ab = A + sA * blockIdx.z;
    const __half* Bb = B + sB * blockIdx.z;
    const int bm = blockIdx.y * BM;
    const int bn = blockIdx.x * BN;
    const int KT = K / BK;

    const uint32_t smem_base = smem_u32(sm);

    // Per-thread cp.async coordinates (same for every chunk / stage):
    // idx = i*256+tid : row = idx>>3 (0..127), seg = idx&7 (16B chunk in row)
    const int ldRow = tid >> 3;                      // wait, recomputed below
    (void)ldRow;
    const int cRow = tid >> 3;        // base row for i=0 (rows advance by 32/i)
    const int cSeg = tid & 7;
    const uint32_t cOffBase = (uint32_t)(((cSeg ^ (cRow & 7)) << 4));
    (void)cOffBase;

    // ldmatrix per-lane row/chunk precompute (row&7 == lane&7 for all bases).
    const int xorv = lane & 7;
    const int rowA = wm * 64 + (lane & 7) + ((lane >> 3) & 1) * 8;
    const int selA = lane >> 4;                   // 0:c0 1:c1
    const int rowB = wn * 32 + (lane & 7) + ((lane >> 4) & 1) * 8;
    const int selB = (lane >> 3) & 1;             // 0:c0 1:c1

    // One chunk of a stage load: A-row-group i and B-row-group i (i = 0..3).
    // Full stage = 4 chunks. Chunk c of row r -> physical chunk c ^ (r & 7).
#define LOAD_CHUNK(s, i) do {                                                  \
        const uint32_t _base = smem_base + (uint32_t)(((s) % NST) * STAGE_H * 2); \
        const uint32_t _bB   = _base + (uint32_t)(TILE_H * 2);                 \
        const int _idx = (i) * 256 + tid;                                      \
        const int _row = _idx >> 3;                                            \
        const int _seg = _idx & 7;                                             \
        const uint32_t _soff = (uint32_t)(_row * 128 +                         \
                               ((_seg ^ (_row & 7)) << 4));                    \
        const __half* _ga = Ab + (size_t)(bm + _row) * ldA + (s) * BK + _seg * 8; \
        const __half* _gb = Bb + (size_t)(bn + _row) * ldB + (s) * BK + _seg * 8; \
        asm volatile("cp.async.cg.shared.global [%0], [%1], 16;"               \
                     :: "r"(_base + _soff), "l"(_ga));                         \
        asm volatile("cp.async.cg.shared.global [%0], [%1], 16;"               \
                     :: "r"(_bB + _soff), "l"(_gb));                           \
    } while (0)

#define LOAD_STAGE(s) do {                                                     \
        LOAD_CHUNK(s, 0); LOAD_CHUNK(s, 1); LOAD_CHUNK(s, 2); LOAD_CHUNK(s, 3);\
        asm volatile("cp.async.commit_group;" ::: "memory");                   \
    } while (0)

    float acc[4][4][4];
    #pragma unroll
    for (int i = 0; i < 4; i++)
        #pragma unroll
        for (int j = 0; j < 4; j++)
            #pragma unroll
            for (int r = 0; r < 4; r++) acc[i][j][r] = 0.0f;

    LOAD_STAGE(0);
    LOAD_STAGE(1);

    for (int k0 = 0; k0 < KT; k0++) {
        if (k0 + 1 < KT) asm volatile("cp.async.wait_group 1;" ::: "memory");
        else             asm volatile("cp.async.wait_group 0;" ::: "memory");
        __syncthreads();

        const bool doLoad = (k0 + 2 < KT);
        const uint32_t stA = smem_base + (uint32_t)((k0 % NST) * STAGE_H * 2);
        const uint32_t stB = stA + (uint32_t)(TILE_H * 2);
        const uint32_t aRowAddr = stA + (uint32_t)(rowA * 128);
        const uint32_t bRowAddr = stB + (uint32_t)(rowB * 128);

        #pragma unroll
        for (int ks = 0; ks < BK / 16; ks++) {
            // spread next-stage global loads across the 4 ks iterations
            if (doLoad) {
                LOAD_CHUNK(k0 + 2, ks);
                if (ks == 3)
                    asm volatile("cp.async.commit_group;" ::: "memory");
            }

            const uint32_t offA = (uint32_t)(((2 * ks + selA) ^ xorv) << 4);
            const uint32_t offB = (uint32_t)(((2 * ks + selB) ^ xorv) << 4);
            uint32_t a[4][4], b[4][2];
            // B first: first MMA depends on b[0] too, and B is the shorter batch
            #pragma unroll
            for (int p = 0; p < 2; p++)
                LDMATRIX_X4(b[2 * p][0], b[2 * p][1], b[2 * p + 1][0], b[2 * p + 1][1],
                            bRowAddr + (uint32_t)(p * 16 * 128) + offB);
            #pragma unroll
            for (int mf = 0; mf < 4; mf++)
                LDMATRIX_X4(a[mf][0], a[mf][1], a[mf][2], a[mf][3],
                            aRowAddr + (uint32_t)(mf * 16 * 128) + offA);
            #pragma unroll
            for (int mf = 0; mf < 4; mf++)
                #pragma unroll
                for (int nf = 0; nf < 4; nf++)
                    asm volatile(
                        "mma.sync.aligned.m16n8k16.row.col.f32.f16.f16.f32 "
                        "{%0,%1,%2,%3}, {%4,%5,%6,%7}, {%8,%9}, {%0,%1,%2,%3};"
                        : "+f"(acc[mf][nf][0]), "+f"(acc[mf][nf][1]),
                          "+f"(acc[mf][nf][2]), "+f"(acc[mf][nf][3])
                        : "r"(a[mf][0]), "r"(a[mf][1]), "r"(a[mf][2]), "r"(a[mf][3]),
                          "r"(b[nf][0]), "r"(b[nf][1]));
        }
    }
#undef LOAD_STAGE
#undef LOAD_CHUNK

    // Epilogue: direct float2 / half2 stores.
    const int mBase = bm + wm * 64 + g;
    const int nBase = bn + wn * 32 + 2 * tig;
    #pragma unroll
    for (int mf = 0; mf < 4; mf++) {
        #pragma unroll
        for (int nf = 0; nf < 4; nf++) {
            const float v0 = acc[mf][nf][0] * alpha, v1 = acc[mf][nf][1] * alpha;
            const float v2 = acc[mf][nf][2] * alpha, v3 = acc[mf][nf][3] * alpha;
            const size_t r0 = (size_t)(mBase + mf * 16) * ldC + nBase + nf * 8;
            const size_t r1 = r0 + 8 * (size_t)ldC;
            if (OUT_HALF) {
                __half* Ch = (__half*)Cv + sC * blockIdx.z;
                *reinterpret_cast<__half2*>(&Ch[r0]) =
                    __float22half2_rn(make_float2(v0, v1));
                *reinterpret_cast<__half2*>(&Ch[r1]) =
                    __float22half2_rn(make_float2(v2, v3));
            } else {
                float* Cf = (float*)Cv + sC * blockIdx.z;
                *reinterpret_cast<float2*>(&Cf[r0]) = make_float2(v0, v1);
                *reinterpret_cast<float2*>(&Cf[r1]) = make_float2(v2, v3);
            }
        }
    }
}

// ---------------------------------------------------------------------------
// Fused fp32 -> fp16 convert for x, Wq, Wk, Wv in ONE launch.
// Block map: [0,4096) x ; [4096,4608) Wq ; [4608,5120) Wk ; [5120,5632) Wv.
// ---------------------------------------------------------------------------
__global__ __launch_bounds__(256)
void cvt_all_kernel(const float4* __restrict__ x,  uint4* __restrict__ xh,
                    const float4* __restrict__ wq, const float4* __restrict__ wk,
                    uint4* __restrict__ wqk,
                    const float4* __restrict__ wv, uint4* __restrict__ wvh)
{
    const int b = blockIdx.x;
    const float4* src;
    uint4* dst;
    int off;
    if (b < 4096)      { src = x;  dst = xh;  off = b; }
    else if (b < 4608) { src = wq; dst = wqk; off = b - 4096; }
    else if (b < 5120) { src = wk; dst = wqk + (size_t)(DH * DIN) / 8; off = b - 4608; }
    else               { src = wv; dst = wvh; off = b - 5120; }

    const int i = off * 256 + threadIdx.x;
    const float4 u = src[2 * i], v = src[2 * i + 1];
    __half2 h0 = __float22half2_rn(make_float2(u.x, u.y));
    __half2 h1 = __float22half2_rn(make_float2(u.z, u.w));
    __half2 h2 = __float22half2_rn(make_float2(v.x, v.y));
    __half2 h3 = __float22half2_rn(make_float2(v.z, v.w));
    uint4 o;
    o.x = *reinterpret_cast<uint32_t*>(&h0);
    o.y = *reinterpret_cast<uint32_t*>(&h1);
    o.z = *reinterpret_cast<uint32_t*>(&h2);
    o.w = *reinterpret_cast<uint32_t*>(&h3);
    dst[i] = o;
}

// ---------------------------------------------------------------------------
// Row softmax: read fp32 scores, write fp16 attn.
// ---------------------------------------------------------------------------
__global__ __launch_bounds__(256)
void softmax_kernel(const float* __restrict__ S, __half* __restrict__ P)
{
    const float* row = S + (size_t)blockIdx.x * SEQ;
    __half*     orow = P + (size_t)blockIdx.x * SEQ;
    const int tid  = threadIdx.x;
    const int lane = tid & 31;
    const int warp = tid >> 5;

    float4 v0 = reinterpret_cast<const float4*>(row)[2 * tid];
    float4 v1 = reinterpret_cast<const float4*>(row)[2 * tid + 1];

    __shared__ float red[8];

    float m = fmaxf(fmaxf(fmaxf(v0.x, v0.y), fmaxf(v0.z, v0.w)),
                    fmaxf(fmaxf(v1.x, v1.y), fmaxf(v1.z, v1.w)));
    #pragma unroll
    for (int o = 16; o > 0; o >>= 1) m = fmaxf(m, __shfl_xor_sync(0xFFFFFFFFu, m, o));
    if (lane == 0) red[warp] = m;
    __syncthreads();
    m = red[0];
    #pragma unroll
    for (int w = 1; w < 8; w++) m = fmaxf(m, red[w]);
    __syncthreads();

    v0.x = __expf(v0.x - m); v0.y = __expf(v0.y - m);
    v0.z = __expf(v0.z - m); v0.w = __expf(v0.w - m);
    v1.x = __expf(v1.x - m); v1.y = __expf(v1.y - m);
    v1.z = __expf(v1.z - m); v1.w = __expf(v1.w - m);

    float s = (v0.x + v0.y + v0.z + v0.w) + (v1.x + v1.y + v1.z + v1.w);
    #pragma unroll
    for (int o = 16; o > 0; o >>= 1) s += __shfl_xor_sync(0xFFFFFFFFu, s, o);
    if (lane == 0) red[warp] = s;
    __syncthreads();
    s = red[0];
    #pragma unroll
    for (int w = 1; w < 8; w++) s += red[w];

    const float inv = 1.0f / s;
    __half2 h0 = __float22half2_rn(make_float2(v0.x * inv, v0.y * inv));
    __half2 h1 = __float22half2_rn(make_float2(v0.z * inv, v0.w * inv));
    __half2 h2 = __float22half2_rn(make_float2(v1.x * inv, v1.y * inv));
    __half2 h3 = __float22half2_rn(make_float2(v1.z * inv, v1.w * inv));
    uint4 o;
    o.x = *reinterpret_cast<uint32_t*>(&h0);
    o.y = *reinterpret_cast<uint32_t*>(&h1);
    o.z = *reinterpret_cast<uint32_t*>(&h2);
    o.w = *reinterpret_cast<uint32_t*>(&h3);
    reinterpret_cast<uint4*>(orow)[tid] = o;
}

// ---------------------------------------------------------------------------
extern "C" void kernel_launch(void* const* d_in, const int* in_sizes, int n_in,
                              void* d_out, int out_size)
{
    (void)in_sizes; (void)n_in; (void)out_size;

    const float* x  = (const float*)d_in[0];
    const float* Wq = (const float*)d_in[1];
    const float* Wk = (const float*)d_in[2];
    const float* Wv = (const float*)d_in[3];
    float*       out = (float*)d_out;

    __half *xh, *wqk, *wv, *QK, *Vt, *At;
    float *Sc;
    cudaGetSymbolAddress((void**)&xh,  g_xh);
    cudaGetSymbolAddress((void**)&wqk, g_Wqk);
    cudaGetSymbolAddress((void**)&wv,  g_Wv);
    cudaGetSymbolAddress((void**)&QK,  g_QK);
    cudaGetSymbolAddress((void**)&Vt,  g_Vt);
    cudaGetSymbolAddress((void**)&Sc,  g_Sc);
    cudaGetSymbolAddress((void**)&At,  g_At);

    cudaFuncSetAttribute(gemm_h16_nt<true>,
                         cudaFuncAttributeMaxDynamicSharedMemorySize, SMEM_BYTES);
    cudaFuncSetAttribute(gemm_h16_nt<false>,
                         cudaFuncAttributeMaxDynamicSharedMemorySize, SMEM_BYTES);

    // 0) convert all inputs to fp16, one launch
    cvt_all_kernel<<<5632, 256>>>((const float4*)x,  (uint4*)xh,
                                  (const float4*)Wq, (const float4*)Wk,
                                  (uint4*)wqk,
                                  (const float4*)Wv, (uint4*)wv);

    // 1) [Q|K] = xh @ [Wq;Wk]^T : one GEMM, N = 2*DH, fp16 out
    {
        dim3 grid((2 * DH) / BN, (NB * SEQ) / BM, 1);     // (16, 64)
        gemm_h16_nt<true><<<grid, 256, SMEM_BYTES>>>(xh, wqk, QK, DIN,
                                                     DIN, DIN, 2 * DH, 1.0f,
                                                     0, 0, 0);
    }

    // 2) V^T_b = Wv @ x_b^T : M=DH, N=SEQ, K=DIN (per batch), fp16 out
    {
        dim3 grid(SEQ / BN, DH / BM, NB);                 // (16, 8, 4)
        gemm_h16_nt<true><<<grid, 256, SMEM_BYTES>>>(wv, xh, Vt, DIN,
                                                     DIN, DIN, SEQ, 1.0f,
                                                     0, (size_t)SEQ * DIN,
                                                     (size_t)DH * SEQ);
    }

    // 3) scores_b = (Q_b @ K_b^T) / sqrt(SEQ), fp32 out
    {
        const float scale = 1.0f / sqrtf((float)SEQ);
        dim3 grid(SEQ / BN, SEQ / BM, NB);                // (16, 16, 4)
        gemm_h16_nt<false><<<grid, 256, SMEM_BYTES>>>(QK, QK + DH, Sc, DH,
                                                      2 * DH, 2 * DH, SEQ, scale,
                                                      (size_t)SEQ * 2 * DH,
                                                      (size_t)SEQ * 2 * DH,
                                                      (size_t)SEQ * SEQ);
    }

    // 4) softmax: fp32 scores -> fp16 attn
    softmax_kernel<<<NB * SEQ, 256>>>(Sc, At);

    // 5) out_b = attn_b @ (V^T_b)^T : M=SEQ, N=DH, K=SEQ, fp32 out
    {
        dim3 grid(DH / BN, SEQ / BM, NB);                 // (8, 16, 4)
        gemm_h16_nt<false><<<grid, 256, SMEM_BYTES>>>(At, Vt, out, SEQ,
                                                      SEQ, SEQ, DH, 1.0f,
                                                      (size_t)SEQ * SEQ,
                                                      (size_t)DH * SEQ,
                                                      (size_t)SEQ * DH);
    }
}